// round 3
// baseline (speedup 1.0000x reference)
#include <cuda_runtime.h>

#define T_STEPS 2048
#define HV 32
#define HKC 16
#define DHEAD 64
#define CONV_DIM_C 4096
#define KEY_DIM_C 1024
#define NCHUNK 32
#define SP 68          // smem row stride (floats), 16B-aligned

// ---- scratch (static __device__, no allocation) ----
__device__ float g_qn[T_STEPS * HKC * DHEAD];
__device__ float g_kn[T_STEPS * HKC * DHEAD];
__device__ float g_v [T_STEPS * HV * DHEAD];
__device__ float g_g   [T_STEPS * HV];
__device__ float g_beta[T_STEPS * HV];
__device__ float g_Qeff[NCHUNK * HV * 4096];
__device__ float g_G   [NCHUNK * HV * 4096];
__device__ float g_H   [NCHUNK * HV * 4096];
__device__ float g_ST  [NCHUNK * HV * 4096];   // chunk-start states, [v][k] transposed

// ---- f32x2 packed FMA helpers ----
__device__ __forceinline__ void ffma2(unsigned long long& acc,
                                      unsigned long long a, unsigned long long b) {
    asm("fma.rn.f32x2 %0, %1, %2, %0;" : "+l"(acc) : "l"(a), "l"(b));
}
__device__ __forceinline__ float hsum(unsigned long long u) {
    float2 f = *reinterpret_cast<float2*>(&u);
    return f.x + f.y;
}

// Z[r][c] = sum_d X[r][d] * YT[c][d], rows r0..r0+3, cols tx+16*ci.
// Both X and YT row-major stride SP; d-pairs packed as f32x2.
__device__ __forceinline__ void mm64x(const float* __restrict__ X,
                                      const float* __restrict__ YT,
                                      int r0, int tx, unsigned long long* __restrict__ acc)
{
#pragma unroll
    for (int d = 0; d < 64; d += 4) {
        ulonglong2 x0 = *(const ulonglong2*)(X + (r0 + 0) * SP + d);
        ulonglong2 x1 = *(const ulonglong2*)(X + (r0 + 1) * SP + d);
        ulonglong2 x2 = *(const ulonglong2*)(X + (r0 + 2) * SP + d);
        ulonglong2 x3 = *(const ulonglong2*)(X + (r0 + 3) * SP + d);
        ulonglong2 y0 = *(const ulonglong2*)(YT + (tx +  0) * SP + d);
        ulonglong2 y1 = *(const ulonglong2*)(YT + (tx + 16) * SP + d);
        ulonglong2 y2 = *(const ulonglong2*)(YT + (tx + 32) * SP + d);
        ulonglong2 y3 = *(const ulonglong2*)(YT + (tx + 48) * SP + d);
        ffma2(acc[ 0], x0.x, y0.x); ffma2(acc[ 0], x0.y, y0.y);
        ffma2(acc[ 1], x0.x, y1.x); ffma2(acc[ 1], x0.y, y1.y);
        ffma2(acc[ 2], x0.x, y2.x); ffma2(acc[ 2], x0.y, y2.y);
        ffma2(acc[ 3], x0.x, y3.x); ffma2(acc[ 3], x0.y, y3.y);
        ffma2(acc[ 4], x1.x, y0.x); ffma2(acc[ 4], x1.y, y0.y);
        ffma2(acc[ 5], x1.x, y1.x); ffma2(acc[ 5], x1.y, y1.y);
        ffma2(acc[ 6], x1.x, y2.x); ffma2(acc[ 6], x1.y, y2.y);
        ffma2(acc[ 7], x1.x, y3.x); ffma2(acc[ 7], x1.y, y3.y);
        ffma2(acc[ 8], x2.x, y0.x); ffma2(acc[ 8], x2.y, y0.y);
        ffma2(acc[ 9], x2.x, y1.x); ffma2(acc[ 9], x2.y, y1.y);
        ffma2(acc[10], x2.x, y2.x); ffma2(acc[10], x2.y, y2.y);
        ffma2(acc[11], x2.x, y3.x); ffma2(acc[11], x2.y, y3.y);
        ffma2(acc[12], x3.x, y0.x); ffma2(acc[12], x3.y, y0.y);
        ffma2(acc[13], x3.x, y1.x); ffma2(acc[13], x3.y, y1.y);
        ffma2(acc[14], x3.x, y2.x); ffma2(acc[14], x3.y, y2.y);
        ffma2(acc[15], x3.x, y3.x); ffma2(acc[15], x3.y, y3.y);
    }
}

// ---------------------------------------------------------------------------
// Kernel 1: conv1d(W=4)+silu+split+l2norm. 4 time-rows per CTA (row reuse).
// grid = (4 channel-quarters, T/4), 256 threads, 4 channels/thread.
// ---------------------------------------------------------------------------
__global__ __launch_bounds__(256) void conv_kernel(
    const float* __restrict__ x,
    const float* __restrict__ cstate,
    const float* __restrict__ wgt)
{
    const int t0 = blockIdx.y * 4;
    const int c  = blockIdx.x * 1024 + threadIdx.x * 4;

    float4 w[4];
#pragma unroll
    for (int j = 0; j < 4; j++) w[j] = *(const float4*)(wgt + (size_t)(c + j) * 4);

    float4 xr[7];
#pragma unroll
    for (int rr = 0; rr < 7; rr++) {
        int r = t0 - 3 + rr;
        xr[rr] = (r >= 0) ? *(const float4*)(x + (size_t)r * CONV_DIM_C + c)
                          : *(const float4*)(cstate + (size_t)(r + 3) * CONV_DIM_C + c);
    }

    float acc[4][4];
#pragma unroll
    for (int tt = 0; tt < 4; tt++) {
        float xv0[4] = {xr[tt].x, xr[tt].y, xr[tt].z, xr[tt].w};
        float xv1[4] = {xr[tt+1].x, xr[tt+1].y, xr[tt+1].z, xr[tt+1].w};
        float xv2[4] = {xr[tt+2].x, xr[tt+2].y, xr[tt+2].z, xr[tt+2].w};
        float xv3[4] = {xr[tt+3].x, xr[tt+3].y, xr[tt+3].z, xr[tt+3].w};
#pragma unroll
        for (int j = 0; j < 4; j++) {
            float s = xv0[j] * w[j].x;
            s = fmaf(xv1[j], w[j].y, s);
            s = fmaf(xv2[j], w[j].z, s);
            s = fmaf(xv3[j], w[j].w, s);
            acc[tt][j] = s / (1.f + __expf(-s));   // silu
        }
    }

    if (c < 2 * KEY_DIM_C) {
        // l2norm over 64-channel groups = 16 lanes (4ch each), per tt
        float ss[4];
#pragma unroll
        for (int tt = 0; tt < 4; tt++) {
            float s = 0.f;
#pragma unroll
            for (int j = 0; j < 4; j++) s = fmaf(acc[tt][j], acc[tt][j], s);
            s += __shfl_xor_sync(0xffffffffu, s, 1);
            s += __shfl_xor_sync(0xffffffffu, s, 2);
            s += __shfl_xor_sync(0xffffffffu, s, 4);
            s += __shfl_xor_sync(0xffffffffu, s, 8);
            ss[tt] = rsqrtf(s + 1e-6f);
        }
        const bool isq = (c < KEY_DIM_C);
#pragma unroll
        for (int tt = 0; tt < 4; tt++) {
            float sc = isq ? ss[tt] * 0.125f : ss[tt];
            float* dst = isq ? (g_qn + (size_t)(t0 + tt) * 1024 + c)
                             : (g_kn + (size_t)(t0 + tt) * 1024 + (c - KEY_DIM_C));
            *(float4*)dst = make_float4(acc[tt][0]*sc, acc[tt][1]*sc, acc[tt][2]*sc, acc[tt][3]*sc);
        }
    } else {
#pragma unroll
        for (int tt = 0; tt < 4; tt++) {
            float* dst = g_v + (size_t)(t0 + tt) * 2048 + (c - 2048);
            *(float4*)dst = make_float4(acc[tt][0], acc[tt][1], acc[tt][2], acc[tt][3]);
        }
    }
}

// ---------------------------------------------------------------------------
// Kernel 2: gates
// ---------------------------------------------------------------------------
__global__ void gates_kernel(
    const float* __restrict__ b, const float* __restrict__ a,
    const float* __restrict__ alog, const float* __restrict__ dtb)
{
    int i = blockIdx.x * blockDim.x + threadIdx.x;
    if (i >= T_STEPS * HV) return;
    int h = i & 31;
    g_beta[i] = 1.f / (1.f + expf(-b[i]));
    float xx = a[i] + dtb[h];
    float sp = (xx > 20.f) ? xx : log1pf(expf(xx));
    g_g[i] = -expf(alog[h]) * sp;
}

// ---------------------------------------------------------------------------
// Kernel 3: per-chunk WY-form precompute. 1024 CTAs, 256 threads, 2 CTA/SM.
// ---------------------------------------------------------------------------
__global__ __launch_bounds__(256, 2) void chunk_kernel(float* __restrict__ out)
{
    extern __shared__ float sm[];
    float* sK   = sm;                 // [64][SP] K row-major
    float* sKT  = sK  + 64 * SP;      // [64][SP] K^T (later Cbar^T)
    float* sQr  = sKT + 64 * SP;      // [64][SP] q normalized+scaled
    float* sM   = sQr + 64 * SP;      // [64][SP] M, later Attn
    float* sWT  = sM  + 64 * SP;      // [64][SP] W^T (solved)
    float* sPT  = sWT + 64 * SP;      // [64][SP] V^T raw, then P^T (solved)
    float* scg  = sPT + 64 * SP;      // [64]
    float* sE   = scg  + 64;
    float* sBeta= sE   + 64;
    float* sBE  = sBeta+ 64;
    float* sTmp = sBE  + 64;

    const int cid = blockIdx.x;
    const int i = cid >> 5;
    const int h = cid & 31;
    const int tid = threadIdx.x;
    const int ty = tid >> 4, tx = tid & 15;
    const int r0 = ty * 4;

    // ---- load K (+transpose), Q, V^T ----
    const float* Kg = g_kn + (size_t)(i * 64) * 1024 + (h >> 1) * 64;
    const float* Qg = g_qn + (size_t)(i * 64) * 1024 + (h >> 1) * 64;
    const float* Vg = g_v  + (size_t)(i * 64) * 2048 + h * 64;
    for (int idx = tid; idx < 64 * 16; idx += 256) {
        int r = idx >> 4, c4 = (idx & 15) << 2;
        float4 kv = *(const float4*)(Kg + (size_t)r * 1024 + c4);
        sK[r * SP + c4 + 0] = kv.x; sK[r * SP + c4 + 1] = kv.y;
        sK[r * SP + c4 + 2] = kv.z; sK[r * SP + c4 + 3] = kv.w;
        sKT[(c4 + 0) * SP + r] = kv.x; sKT[(c4 + 1) * SP + r] = kv.y;
        sKT[(c4 + 2) * SP + r] = kv.z; sKT[(c4 + 3) * SP + r] = kv.w;
        float4 qv = *(const float4*)(Qg + (size_t)r * 1024 + c4);
        sQr[r * SP + c4 + 0] = qv.x; sQr[r * SP + c4 + 1] = qv.y;
        sQr[r * SP + c4 + 2] = qv.z; sQr[r * SP + c4 + 3] = qv.w;
        float4 vv = *(const float4*)(Vg + (size_t)r * 2048 + c4);
        sPT[(c4 + 0) * SP + r] = vv.x; sPT[(c4 + 1) * SP + r] = vv.y;
        sPT[(c4 + 2) * SP + r] = vv.z; sPT[(c4 + 3) * SP + r] = vv.w;
    }
    if (tid < 64) {
        scg[tid]   = g_g   [(size_t)(i * 64 + tid) * 32 + h];
        sBeta[tid] = g_beta[(size_t)(i * 64 + tid) * 32 + h];
    }
    __syncthreads();

    // ---- inclusive scan of log-decay ----
#pragma unroll
    for (int off = 1; off < 64; off <<= 1) {
        float v = 0.f;
        if (tid < 64) v = scg[tid] + ((tid >= off) ? scg[tid - off] : 0.f);
        __syncthreads();
        if (tid < 64) scg[tid] = v;
        __syncthreads();
    }
    if (tid < 64) {
        float e = __expf(scg[tid]);
        sE[tid] = e;
        sBE[tid] = e * sBeta[tid];
        sTmp[tid] = __expf(scg[63] - scg[tid]);
    }
    __syncthreads();

    unsigned long long acc[16];

    // ---- (a) M = masked-scaled K K^T ----
#pragma unroll
    for (int j = 0; j < 16; j++) acc[j] = 0ull;
    mm64x(sK, sK, r0, tx, acc);
#pragma unroll
    for (int ri = 0; ri < 4; ri++) {
        int t = r0 + ri;
        float bt = sBeta[t], ct = scg[t];
#pragma unroll
        for (int ci = 0; ci < 4; ci++) {
            int s = tx + 16 * ci;
            sM[t * SP + s] = (s < t) ? bt * hsum(acc[ri * 4 + ci]) * __expf(ct - scg[s]) : 0.f;
        }
    }
    __syncthreads();

    // ---- solve (I+M)X = RHS, column-per-thread, registers, no barriers ----
    if (tid < 128) {
        const bool isW = (tid < 64);
        const int  cc  = isW ? tid : (tid - 64);
        const float* src = isW ? (sKT + cc * SP) : (sPT + cc * SP);
        float xcol[64];
#pragma unroll
        for (int t = 0; t < 64; t++) {
            float r = (isW ? sBE[t] : sBeta[t]) * src[t];
            const float* Mr = sM + t * SP;
#pragma unroll
            for (int s = 0; s < t; s++) r = fmaf(-Mr[s], xcol[s], r);
            xcol[t] = r;
        }
        float* dst = isW ? (sWT + cc * SP) : (sPT + cc * SP);
#pragma unroll
        for (int t = 0; t < 64; t++) dst[t] = xcol[t];
    }
    __syncthreads();

    // ---- (d) Attn = masked-scaled Q K^T -> sM; scale sKT -> Cbar^T ----
#pragma unroll
    for (int j = 0; j < 16; j++) acc[j] = 0ull;
    mm64x(sQr, sK, r0, tx, acc);
    for (int idx = tid; idx < 4096; idx += 256) {
        int r = idx >> 6, s = idx & 63;
        sKT[r * SP + s] *= sTmp[s];
    }
#pragma unroll
    for (int ri = 0; ri < 4; ri++) {
        int t = r0 + ri;
        float ct = scg[t];
#pragma unroll
        for (int ci = 0; ci < 4; ci++) {
            int s = tx + 16 * ci;
            sM[t * SP + s] = (s <= t) ? hsum(acc[ri * 4 + ci]) * __expf(ct - scg[s]) : 0.f;
        }
    }
    __syncthreads();

    const size_t base = ((size_t)(i * 32 + h)) << 12;

    // ---- (e) Qeff = E*Q - Attn@W ----
#pragma unroll
    for (int j = 0; j < 16; j++) acc[j] = 0ull;
    mm64x(sM, sWT, r0, tx, acc);
#pragma unroll
    for (int ri = 0; ri < 4; ri++) {
        int t = r0 + ri;
        float et = sE[t];
#pragma unroll
        for (int ci = 0; ci < 4; ci++) {
            int s = tx + 16 * ci;
            g_Qeff[base + t * 64 + s] = fmaf(et, sQr[t * SP + s], -hsum(acc[ri * 4 + ci]));
        }
    }

    // ---- (f) Ointra = Attn@P -> out ----
#pragma unroll
    for (int j = 0; j < 16; j++) acc[j] = 0ull;
    mm64x(sM, sPT, r0, tx, acc);
#pragma unroll
    for (int ri = 0; ri < 4; ri++) {
        int t = r0 + ri;
#pragma unroll
        for (int ci = 0; ci < 4; ci++) {
            int s = tx + 16 * ci;
            out[(size_t)(i * 64 + t) * 2048 + h * 64 + s] = hsum(acc[ri * 4 + ci]);
        }
    }

    // ---- (g) G = b63*I - Cbar^T @ W ----
#pragma unroll
    for (int j = 0; j < 16; j++) acc[j] = 0ull;
    mm64x(sKT, sWT, r0, tx, acc);
    {
        float b63 = sE[63];
#pragma unroll
        for (int ri = 0; ri < 4; ri++) {
            int k = r0 + ri;
#pragma unroll
            for (int ci = 0; ci < 4; ci++) {
                int s = tx + 16 * ci;
                g_G[base + k * 64 + s] = ((k == s) ? b63 : 0.f) - hsum(acc[ri * 4 + ci]);
            }
        }
    }

    // ---- (h) H = Cbar^T @ P ----
#pragma unroll
    for (int j = 0; j < 16; j++) acc[j] = 0ull;
    mm64x(sKT, sPT, r0, tx, acc);
#pragma unroll
    for (int ri = 0; ri < 4; ri++) {
        int k = r0 + ri;
#pragma unroll
        for (int ci = 0; ci < 4; ci++) {
            int s = tx + 16 * ci;
            g_H[base + k * 64 + s] = hsum(acc[ri * 4 + ci]);
        }
    }
}

// ---------------------------------------------------------------------------
// Kernel 4: state pass. S_{i+1} = G_i S_i + H_i; writes all chunk-start
// states transposed to g_ST. 64 CTAs = (head, v-half), 256 threads.
// ---------------------------------------------------------------------------
__global__ __launch_bounds__(256) void state_kernel(const float* __restrict__ S0)
{
    __shared__ float sG[64 * SP];
    __shared__ float sSa[32 * SP];
    __shared__ float sSb[32 * SP];

    const int h = blockIdx.x >> 1;
    const int vh = blockIdx.x & 1;
    const int vbase = vh * 32;
    const int tid = threadIdx.x;
    const int ty = tid >> 3, tx = tid & 7;   // ty 0..31, tx 0..7
    const int r0 = 2 * ty;                   // k rows (2 per thread)

    // init ST[vloc][k] = S0[h][k][vbase+vloc]
    for (int idx = tid; idx < 2048; idx += 256) {
        int k = idx >> 5, vloc = idx & 31;
        sSa[vloc * SP + k] = S0[(size_t)h * 4096 + k * 64 + vbase + vloc];
    }
    // preload G_0
    {
        const size_t b0 = ((size_t)h) << 12;
        for (int idx = tid; idx < 1024; idx += 256) {
            int r = idx >> 4, c4 = (idx & 15) << 2;
            float4 g = *(const float4*)(g_G + b0 + r * 64 + c4);
            sG[r * SP + c4 + 0] = g.x; sG[r * SP + c4 + 1] = g.y;
            sG[r * SP + c4 + 2] = g.z; sG[r * SP + c4 + 3] = g.w;
        }
    }
    float hcur[8];
    {
        const size_t b0 = ((size_t)h) << 12;
#pragma unroll
        for (int ri = 0; ri < 2; ri++)
#pragma unroll
            for (int ci = 0; ci < 4; ci++)
                hcur[ri * 4 + ci] = g_H[b0 + (r0 + ri) * 64 + vbase + tx + 8 * ci];
    }
    __syncthreads();

    float* Scur = sSa;
    float* Snxt = sSb;

    for (int i = 0; i < NCHUNK; i++) {
        const size_t basei = ((size_t)(i * 32 + h)) << 12;
        // write current chunk-start state (transposed layout [v][k])
        for (int idx = tid; idx < 512; idx += 256) {
            int vloc = idx >> 4, k4 = (idx & 15) << 2;
            float4 s = *(const float4*)(Scur + vloc * SP + k4);
            *(float4*)(g_ST + basei + (vbase + vloc) * 64 + k4) = s;
        }
        if (i == NCHUNK - 1) break;

        // prefetch next G/H into regs
        const size_t basen = ((size_t)((i + 1) * 32 + h)) << 12;
        float4 gpre[4];
#pragma unroll
        for (int j = 0; j < 4; j++) {
            int idx = tid + j * 256;
            int r = idx >> 4, c4 = (idx & 15) << 2;
            gpre[j] = *(const float4*)(g_G + basen + r * 64 + c4);
        }
        float hpre[8];
#pragma unroll
        for (int ri = 0; ri < 2; ri++)
#pragma unroll
            for (int ci = 0; ci < 4; ci++)
                hpre[ri * 4 + ci] = g_H[basen + (r0 + ri) * 64 + vbase + tx + 8 * ci];

        // compute Snxt = G_i @ Scur + H_i  (rows r0,r0+1; cols tx+8*ci)
        unsigned long long acc[8];
#pragma unroll
        for (int j = 0; j < 8; j++) acc[j] = 0ull;
#pragma unroll
        for (int d = 0; d < 64; d += 4) {
            ulonglong2 x0 = *(const ulonglong2*)(sG + (r0 + 0) * SP + d);
            ulonglong2 x1 = *(const ulonglong2*)(sG + (r0 + 1) * SP + d);
            ulonglong2 y0 = *(const ulonglong2*)(Scur + (tx +  0) * SP + d);
            ulonglong2 y1 = *(const ulonglong2*)(Scur + (tx +  8) * SP + d);
            ulonglong2 y2 = *(const ulonglong2*)(Scur + (tx + 16) * SP + d);
            ulonglong2 y3 = *(const ulonglong2*)(Scur + (tx + 24) * SP + d);
            ffma2(acc[0], x0.x, y0.x); ffma2(acc[0], x0.y, y0.y);
            ffma2(acc[1], x0.x, y1.x); ffma2(acc[1], x0.y, y1.y);
            ffma2(acc[2], x0.x, y2.x); ffma2(acc[2], x0.y, y2.y);
            ffma2(acc[3], x0.x, y3.x); ffma2(acc[3], x0.y, y3.y);
            ffma2(acc[4], x1.x, y0.x); ffma2(acc[4], x1.y, y0.y);
            ffma2(acc[5], x1.x, y1.x); ffma2(acc[5], x1.y, y1.y);
            ffma2(acc[6], x1.x, y2.x); ffma2(acc[6], x1.y, y2.y);
            ffma2(acc[7], x1.x, y3.x); ffma2(acc[7], x1.y, y3.y);
        }
#pragma unroll
        for (int ci = 0; ci < 4; ci++) {
            float o0 = hsum(acc[0 + ci]) + hcur[ci];
            float o1 = hsum(acc[4 + ci]) + hcur[4 + ci];
            *(float2*)(Snxt + (tx + 8 * ci) * SP + r0) = make_float2(o0, o1);
        }
        __syncthreads();
        // commit prefetched G
#pragma unroll
        for (int j = 0; j < 4; j++) {
            int idx = tid + j * 256;
            int r = idx >> 4, c4 = (idx & 15) << 2;
            sG[r * SP + c4 + 0] = gpre[j].x; sG[r * SP + c4 + 1] = gpre[j].y;
            sG[r * SP + c4 + 2] = gpre[j].z; sG[r * SP + c4 + 3] = gpre[j].w;
        }
#pragma unroll
        for (int j = 0; j < 8; j++) hcur[j] = hpre[j];
        float* t2 = Scur; Scur = Snxt; Snxt = t2;
        __syncthreads();
    }
}

// ---------------------------------------------------------------------------
// Kernel 5: O pass (fully parallel). out += Qeff_i @ S_i. 1024 CTAs.
// ---------------------------------------------------------------------------
__global__ __launch_bounds__(256) void opass_kernel(float* __restrict__ out)
{
    __shared__ float sQe[64 * SP];
    __shared__ float sST[64 * SP];

    const int bi = blockIdx.x;
    const int i = bi >> 5;
    const int h = bi & 31;
    const int tid = threadIdx.x;
    const int ty = tid >> 4, tx = tid & 15;
    const int r0 = ty * 4;

    const size_t base = ((size_t)(i * 32 + h)) << 12;
    for (int idx = tid; idx < 1024; idx += 256) {
        int r = idx >> 4, c4 = (idx & 15) << 2;
        float4 q = *(const float4*)(g_Qeff + base + r * 64 + c4);
        sQe[r * SP + c4 + 0] = q.x; sQe[r * SP + c4 + 1] = q.y;
        sQe[r * SP + c4 + 2] = q.z; sQe[r * SP + c4 + 3] = q.w;
        float4 s = *(const float4*)(g_ST + base + r * 64 + c4);
        sST[r * SP + c4 + 0] = s.x; sST[r * SP + c4 + 1] = s.y;
        sST[r * SP + c4 + 2] = s.z; sST[r * SP + c4 + 3] = s.w;
    }
    __syncthreads();

    unsigned long long acc[16];
#pragma unroll
    for (int j = 0; j < 16; j++) acc[j] = 0ull;
    mm64x(sQe, sST, r0, tx, acc);

#pragma unroll
    for (int ri = 0; ri < 4; ri++) {
        int t = r0 + ri;
        float* op = out + (size_t)(i * 64 + t) * 2048 + h * 64;
#pragma unroll
        for (int ci = 0; ci < 4; ci++) {
            int s = tx + 16 * ci;
            op[s] += hsum(acc[ri * 4 + ci]);
        }
    }
}

// ---------------------------------------------------------------------------
extern "C" void kernel_launch(void* const* d_in, const int* in_sizes, int n_in,
                              void* d_out, int out_size)
{
    const float* x    = (const float*)d_in[0];
    const float* cs   = (const float*)d_in[1];
    const float* s0   = (const float*)d_in[2];
    const float* b    = (const float*)d_in[3];
    const float* a    = (const float*)d_in[4];
    const float* w    = (const float*)d_in[5];
    const float* alog = (const float*)d_in[6];
    const float* dtb  = (const float*)d_in[7];

    const int smem_bytes = (6 * 64 * SP + 5 * 64) * sizeof(float);  // ~105.7 KB
    cudaFuncSetAttribute(chunk_kernel,
                         cudaFuncAttributeMaxDynamicSharedMemorySize, smem_bytes);

    conv_kernel<<<dim3(4, T_STEPS / 4), 256>>>(x, cs, w);
    gates_kernel<<<(T_STEPS * HV + 255) / 256, 256>>>(b, a, alog, dtb);
    chunk_kernel<<<NCHUNK * HV, 256, smem_bytes>>>((float*)d_out);
    state_kernel<<<64, 256>>>(s0);
    opass_kernel<<<NCHUNK * HV, 256>>>((float*)d_out);
}

// round 4
// speedup vs baseline: 2.3095x; 2.3095x over previous
#include <cuda_runtime.h>
#include <cstdint>

#define T_STEPS 2048
#define HV 32
#define HKC 16
#define DHEAD 64
#define CONV_DIM_C 4096
#define KEY_DIM_C 1024
#define NCHUNK 32
#define SP 68          // smem row stride (floats), 16B-aligned

// ---- scratch (static __device__, no allocation) ----
__device__ float g_qn[T_STEPS * HKC * DHEAD];
__device__ float g_kn[T_STEPS * HKC * DHEAD];
__device__ float g_v [T_STEPS * HV * DHEAD];
__device__ float g_g   [T_STEPS * HV];
__device__ float g_beta[T_STEPS * HV];
__device__ float g_Qeff[NCHUNK * HV * 4096];
__device__ float g_G   [NCHUNK * HV * 4096];
__device__ float g_H   [NCHUNK * HV * 4096];
__device__ float g_ST  [NCHUNK * HV * 4096];   // chunk-start states, [v][k]

// ---- f32x2 packed FMA helpers ----
__device__ __forceinline__ void ffma2(unsigned long long& acc,
                                      unsigned long long a, unsigned long long b) {
    asm("fma.rn.f32x2 %0, %1, %2, %0;" : "+l"(acc) : "l"(a), "l"(b));
}
__device__ __forceinline__ float hsum(unsigned long long u) {
    float2 f = *reinterpret_cast<float2*>(&u);
    return f.x + f.y;
}

// ---- cp.async helpers ----
__device__ __forceinline__ void cp_async16(void* dst, const void* src) {
    uint32_t d = (uint32_t)__cvta_generic_to_shared(dst);
    asm volatile("cp.async.cg.shared.global [%0], [%1], 16;" :: "r"(d), "l"(src));
}
__device__ __forceinline__ void cp_commit() {
    asm volatile("cp.async.commit_group;");
}
__device__ __forceinline__ void cp_wait0() {
    asm volatile("cp.async.wait_group 0;");
}

// Z[r][c] = sum_d X[r][d] * YT[c][d], rows r0..r0+3, cols tx+16*ci.
__device__ __forceinline__ void mm64x(const float* __restrict__ X,
                                      const float* __restrict__ YT,
                                      int r0, int tx, unsigned long long* __restrict__ acc)
{
#pragma unroll 4
    for (int d = 0; d < 64; d += 4) {
        ulonglong2 x0 = *(const ulonglong2*)(X + (r0 + 0) * SP + d);
        ulonglong2 x1 = *(const ulonglong2*)(X + (r0 + 1) * SP + d);
        ulonglong2 x2 = *(const ulonglong2*)(X + (r0 + 2) * SP + d);
        ulonglong2 x3 = *(const ulonglong2*)(X + (r0 + 3) * SP + d);
        ulonglong2 y0 = *(const ulonglong2*)(YT + (tx +  0) * SP + d);
        ulonglong2 y1 = *(const ulonglong2*)(YT + (tx + 16) * SP + d);
        ulonglong2 y2 = *(const ulonglong2*)(YT + (tx + 32) * SP + d);
        ulonglong2 y3 = *(const ulonglong2*)(YT + (tx + 48) * SP + d);
        ffma2(acc[ 0], x0.x, y0.x); ffma2(acc[ 0], x0.y, y0.y);
        ffma2(acc[ 1], x0.x, y1.x); ffma2(acc[ 1], x0.y, y1.y);
        ffma2(acc[ 2], x0.x, y2.x); ffma2(acc[ 2], x0.y, y2.y);
        ffma2(acc[ 3], x0.x, y3.x); ffma2(acc[ 3], x0.y, y3.y);
        ffma2(acc[ 4], x1.x, y0.x); ffma2(acc[ 4], x1.y, y0.y);
        ffma2(acc[ 5], x1.x, y1.x); ffma2(acc[ 5], x1.y, y1.y);
        ffma2(acc[ 6], x1.x, y2.x); ffma2(acc[ 6], x1.y, y2.y);
        ffma2(acc[ 7], x1.x, y3.x); ffma2(acc[ 7], x1.y, y3.y);
        ffma2(acc[ 8], x2.x, y0.x); ffma2(acc[ 8], x2.y, y0.y);
        ffma2(acc[ 9], x2.x, y1.x); ffma2(acc[ 9], x2.y, y1.y);
        ffma2(acc[10], x2.x, y2.x); ffma2(acc[10], x2.y, y2.y);
        ffma2(acc[11], x2.x, y3.x); ffma2(acc[11], x2.y, y3.y);
        ffma2(acc[12], x3.x, y0.x); ffma2(acc[12], x3.y, y0.y);
        ffma2(acc[13], x3.x, y1.x); ffma2(acc[13], x3.y, y1.y);
        ffma2(acc[14], x3.x, y2.x); ffma2(acc[14], x3.y, y2.y);
        ffma2(acc[15], x3.x, y3.x); ffma2(acc[15], x3.y, y3.y);
    }
}

// ---------------------------------------------------------------------------
// Kernel 1: conv1d(W=4)+silu+split+l2norm. 4 time-rows per CTA.
// ---------------------------------------------------------------------------
__global__ __launch_bounds__(256) void conv_kernel(
    const float* __restrict__ x,
    const float* __restrict__ cstate,
    const float* __restrict__ wgt)
{
    const int t0 = blockIdx.y * 4;
    const int c  = blockIdx.x * 1024 + threadIdx.x * 4;

    float4 w[4];
#pragma unroll
    for (int j = 0; j < 4; j++) w[j] = *(const float4*)(wgt + (size_t)(c + j) * 4);

    float4 xr[7];
#pragma unroll
    for (int rr = 0; rr < 7; rr++) {
        int r = t0 - 3 + rr;
        xr[rr] = (r >= 0) ? *(const float4*)(x + (size_t)r * CONV_DIM_C + c)
                          : *(const float4*)(cstate + (size_t)(r + 3) * CONV_DIM_C + c);
    }

    float acc[4][4];
#pragma unroll
    for (int tt = 0; tt < 4; tt++) {
        float xv0[4] = {xr[tt].x, xr[tt].y, xr[tt].z, xr[tt].w};
        float xv1[4] = {xr[tt+1].x, xr[tt+1].y, xr[tt+1].z, xr[tt+1].w};
        float xv2[4] = {xr[tt+2].x, xr[tt+2].y, xr[tt+2].z, xr[tt+2].w};
        float xv3[4] = {xr[tt+3].x, xr[tt+3].y, xr[tt+3].z, xr[tt+3].w};
#pragma unroll
        for (int j = 0; j < 4; j++) {
            float s = xv0[j] * w[j].x;
            s = fmaf(xv1[j], w[j].y, s);
            s = fmaf(xv2[j], w[j].z, s);
            s = fmaf(xv3[j], w[j].w, s);
            acc[tt][j] = s / (1.f + __expf(-s));
        }
    }

    if (c < 2 * KEY_DIM_C) {
        float ss[4];
#pragma unroll
        for (int tt = 0; tt < 4; tt++) {
            float s = 0.f;
#pragma unroll
            for (int j = 0; j < 4; j++) s = fmaf(acc[tt][j], acc[tt][j], s);
            s += __shfl_xor_sync(0xffffffffu, s, 1);
            s += __shfl_xor_sync(0xffffffffu, s, 2);
            s += __shfl_xor_sync(0xffffffffu, s, 4);
            s += __shfl_xor_sync(0xffffffffu, s, 8);
            ss[tt] = rsqrtf(s + 1e-6f);
        }
        const bool isq = (c < KEY_DIM_C);
#pragma unroll
        for (int tt = 0; tt < 4; tt++) {
            float sc = isq ? ss[tt] * 0.125f : ss[tt];
            float* dst = isq ? (g_qn + (size_t)(t0 + tt) * 1024 + c)
                             : (g_kn + (size_t)(t0 + tt) * 1024 + (c - KEY_DIM_C));
            *(float4*)dst = make_float4(acc[tt][0]*sc, acc[tt][1]*sc, acc[tt][2]*sc, acc[tt][3]*sc);
        }
    } else {
#pragma unroll
        for (int tt = 0; tt < 4; tt++) {
            float* dst = g_v + (size_t)(t0 + tt) * 2048 + (c - 2048);
            *(float4*)dst = make_float4(acc[tt][0], acc[tt][1], acc[tt][2], acc[tt][3]);
        }
    }
}

// ---------------------------------------------------------------------------
// Kernel 2: gates
// ---------------------------------------------------------------------------
__global__ void gates_kernel(
    const float* __restrict__ b, const float* __restrict__ a,
    const float* __restrict__ alog, const float* __restrict__ dtb)
{
    int i = blockIdx.x * blockDim.x + threadIdx.x;
    if (i >= T_STEPS * HV) return;
    int h = i & 31;
    g_beta[i] = 1.f / (1.f + expf(-b[i]));
    float xx = a[i] + dtb[h];
    float sp = (xx > 20.f) ? xx : log1pf(expf(xx));
    g_g[i] = -expf(alog[h]) * sp;
}

// ---------------------------------------------------------------------------
// Kernel 3: per-chunk WY-form precompute. 1024 CTAs, 256 threads, 2 CTA/SM.
// ---------------------------------------------------------------------------
__global__ __launch_bounds__(256, 2) void chunk_kernel(float* __restrict__ out)
{
    extern __shared__ float sm[];
    float* sK   = sm;                 // [64][SP] K row-major
    float* sKT  = sK  + 64 * SP;      // [64][SP] K^T (later Cbar^T)
    float* sQr  = sKT + 64 * SP;      // [64][SP] q normalized+scaled
    float* sM   = sQr + 64 * SP;      // [64][SP] M, later Attn
    float* sWT  = sM  + 64 * SP;      // [64][SP] W^T (solved)
    float* sPT  = sWT + 64 * SP;      // [64][SP] V^T raw, then P^T (solved)
    float* scg  = sPT + 64 * SP;      // [64]
    float* sE   = scg  + 64;
    float* sBeta= sE   + 64;
    float* sBE  = sBeta+ 64;
    float* sTmp = sBE  + 64;

    const int cid = blockIdx.x;
    const int i = cid >> 5;
    const int h = cid & 31;
    const int tid = threadIdx.x;
    const int ty = tid >> 4, tx = tid & 15;
    const int r0 = ty * 4;

    // ---- load K (+transpose), Q, V^T ----
    const float* Kg = g_kn + (size_t)(i * 64) * 1024 + (h >> 1) * 64;
    const float* Qg = g_qn + (size_t)(i * 64) * 1024 + (h >> 1) * 64;
    const float* Vg = g_v  + (size_t)(i * 64) * 2048 + h * 64;
    for (int idx = tid; idx < 64 * 16; idx += 256) {
        int r = idx >> 4, c4 = (idx & 15) << 2;
        float4 kv = *(const float4*)(Kg + (size_t)r * 1024 + c4);
        sK[r * SP + c4 + 0] = kv.x; sK[r * SP + c4 + 1] = kv.y;
        sK[r * SP + c4 + 2] = kv.z; sK[r * SP + c4 + 3] = kv.w;
        sKT[(c4 + 0) * SP + r] = kv.x; sKT[(c4 + 1) * SP + r] = kv.y;
        sKT[(c4 + 2) * SP + r] = kv.z; sKT[(c4 + 3) * SP + r] = kv.w;
        float4 qv = *(const float4*)(Qg + (size_t)r * 1024 + c4);
        sQr[r * SP + c4 + 0] = qv.x; sQr[r * SP + c4 + 1] = qv.y;
        sQr[r * SP + c4 + 2] = qv.z; sQr[r * SP + c4 + 3] = qv.w;
        float4 vv = *(const float4*)(Vg + (size_t)r * 2048 + c4);
        sPT[(c4 + 0) * SP + r] = vv.x; sPT[(c4 + 1) * SP + r] = vv.y;
        sPT[(c4 + 2) * SP + r] = vv.z; sPT[(c4 + 3) * SP + r] = vv.w;
    }
    if (tid < 64) {
        scg[tid]   = g_g   [(size_t)(i * 64 + tid) * 32 + h];
        sBeta[tid] = g_beta[(size_t)(i * 64 + tid) * 32 + h];
    }
    __syncthreads();

    // ---- inclusive scan of log-decay ----
#pragma unroll
    for (int off = 1; off < 64; off <<= 1) {
        float v = 0.f;
        if (tid < 64) v = scg[tid] + ((tid >= off) ? scg[tid - off] : 0.f);
        __syncthreads();
        if (tid < 64) scg[tid] = v;
        __syncthreads();
    }
    if (tid < 64) {
        float e = __expf(scg[tid]);
        sE[tid] = e;
        sBE[tid] = e * sBeta[tid];
        sTmp[tid] = __expf(scg[63] - scg[tid]);
    }
    __syncthreads();

    unsigned long long acc[16];

    // ---- (a) M = masked-scaled K K^T ----
#pragma unroll
    for (int j = 0; j < 16; j++) acc[j] = 0ull;
    mm64x(sK, sK, r0, tx, acc);
#pragma unroll
    for (int ri = 0; ri < 4; ri++) {
        int t = r0 + ri;
        float bt = sBeta[t], ct = scg[t];
#pragma unroll
        for (int ci = 0; ci < 4; ci++) {
            int s = tx + 16 * ci;
            sM[t * SP + s] = (s < t) ? bt * hsum(acc[ri * 4 + ci]) * __expf(ct - scg[s]) : 0.f;
        }
    }
    __syncthreads();

    // ---- solve (I+M)X = RHS. Column-per-thread in SMEM: NO cross-thread
    //      dependency -> no barriers, dynamic loops (small code, no spill).
    if (tid < 128) {
        const bool isW = (tid < 64);
        const int  cc  = tid & 63;
        float* col = (isW ? sWT : sPT) + cc * SP;
        const float* rsrc = sKT + cc * SP;   // only used for W side
        for (int t = 0; t < 64; t++) {
            float r = isW ? sBE[t] * rsrc[t] : sBeta[t] * col[t];
            const float* Mr = sM + t * SP;
            float a0 = 0.f, a1 = 0.f, a2 = 0.f, a3 = 0.f;
            int s = 0;
            for (; s + 4 <= t; s += 4) {
                a0 = fmaf(Mr[s + 0], col[s + 0], a0);
                a1 = fmaf(Mr[s + 1], col[s + 1], a1);
                a2 = fmaf(Mr[s + 2], col[s + 2], a2);
                a3 = fmaf(Mr[s + 3], col[s + 3], a3);
            }
            for (; s < t; s++) a0 = fmaf(Mr[s], col[s], a0);
            col[t] = r - ((a0 + a1) + (a2 + a3));
        }
    }
    __syncthreads();

    // ---- (d) Attn = masked-scaled Q K^T -> sM; scale sKT -> Cbar^T ----
#pragma unroll
    for (int j = 0; j < 16; j++) acc[j] = 0ull;
    mm64x(sQr, sK, r0, tx, acc);
    for (int idx = tid; idx < 4096; idx += 256) {
        int r = idx >> 6, s = idx & 63;
        sKT[r * SP + s] *= sTmp[s];
    }
#pragma unroll
    for (int ri = 0; ri < 4; ri++) {
        int t = r0 + ri;
        float ct = scg[t];
#pragma unroll
        for (int ci = 0; ci < 4; ci++) {
            int s = tx + 16 * ci;
            sM[t * SP + s] = (s <= t) ? hsum(acc[ri * 4 + ci]) * __expf(ct - scg[s]) : 0.f;
        }
    }
    __syncthreads();

    const size_t base = ((size_t)(i * 32 + h)) << 12;

    // ---- (e) Qeff = E*Q - Attn@W ----
#pragma unroll
    for (int j = 0; j < 16; j++) acc[j] = 0ull;
    mm64x(sM, sWT, r0, tx, acc);
#pragma unroll
    for (int ri = 0; ri < 4; ri++) {
        int t = r0 + ri;
        float et = sE[t];
#pragma unroll
        for (int ci = 0; ci < 4; ci++) {
            int s = tx + 16 * ci;
            g_Qeff[base + t * 64 + s] = fmaf(et, sQr[t * SP + s], -hsum(acc[ri * 4 + ci]));
        }
    }

    // ---- (f) Ointra = Attn@P -> out ----
#pragma unroll
    for (int j = 0; j < 16; j++) acc[j] = 0ull;
    mm64x(sM, sPT, r0, tx, acc);
#pragma unroll
    for (int ri = 0; ri < 4; ri++) {
        int t = r0 + ri;
#pragma unroll
        for (int ci = 0; ci < 4; ci++) {
            int s = tx + 16 * ci;
            out[(size_t)(i * 64 + t) * 2048 + h * 64 + s] = hsum(acc[ri * 4 + ci]);
        }
    }

    // ---- (g) G = b63*I - Cbar^T @ W ----
#pragma unroll
    for (int j = 0; j < 16; j++) acc[j] = 0ull;
    mm64x(sKT, sWT, r0, tx, acc);
    {
        float b63 = sE[63];
#pragma unroll
        for (int ri = 0; ri < 4; ri++) {
            int k = r0 + ri;
#pragma unroll
            for (int ci = 0; ci < 4; ci++) {
                int s = tx + 16 * ci;
                g_G[base + k * 64 + s] = ((k == s) ? b63 : 0.f) - hsum(acc[ri * 4 + ci]);
            }
        }
    }

    // ---- (h) H = Cbar^T @ P ----
#pragma unroll
    for (int j = 0; j < 16; j++) acc[j] = 0ull;
    mm64x(sKT, sPT, r0, tx, acc);
#pragma unroll
    for (int ri = 0; ri < 4; ri++) {
        int k = r0 + ri;
#pragma unroll
        for (int ci = 0; ci < 4; ci++) {
            int s = tx + 16 * ci;
            g_H[base + k * 64 + s] = hsum(acc[ri * 4 + ci]);
        }
    }
}

// ---------------------------------------------------------------------------
// Kernel 4: state pass. 32 CTAs (one per head) x 512 threads.
// S_{i+1} = G_i S_i + H_i; emits chunk-start states (transposed) to g_ST.
// G double-buffered via cp.async. Thread block: 4 k-rows x 2 v-cols.
// ---------------------------------------------------------------------------
__global__ __launch_bounds__(512) void state_kernel(const float* __restrict__ S0)
{
    extern __shared__ float sms[];
    float* sG0 = sms;                 // [64][SP]
    float* sG1 = sG0 + 64 * SP;
    float* sS0 = sG1 + 64 * SP;       // [v][k], [64][SP]
    float* sS1 = sS0 + 64 * SP;

    const int h = blockIdx.x;
    const int tid = threadIdx.x;
    const int ry = tid >> 5;          // 0..15
    const int tx = tid & 31;          // 0..31
    const int k0 = ry * 4;

    const size_t hbase = ((size_t)h) << 12;

    // init Scur[v][k] = S0[h][k][v]  (coalesced on v)
    for (int idx = tid; idx < 4096; idx += 512) {
        int k = idx >> 6, v = idx & 63;
        sS0[v * SP + k] = S0[hbase + k * 64 + v];
    }
    // preload G_0 via cp.async
#pragma unroll
    for (int j = 0; j < 2; j++) {
        int seg = tid + j * 512;
        int r = seg >> 4, c4 = (seg & 15) << 2;
        cp_async16(sG0 + r * SP + c4, g_G + hbase + r * 64 + c4);
    }
    cp_commit();
    // preload H_0 into regs
    float hcur[8];
#pragma unroll
    for (int ri = 0; ri < 4; ri++) {
        hcur[ri * 2 + 0] = g_H[hbase + (k0 + ri) * 64 + tx];
        hcur[ri * 2 + 1] = g_H[hbase + (k0 + ri) * 64 + tx + 32];
    }
    cp_wait0();
    __syncthreads();

    float* Scur = sS0; float* Snxt = sS1;
    float* Gcur = sG0; float* Gnxt = sG1;

    for (int i = 0; i < NCHUNK; i++) {
        const size_t basei = ((size_t)(i * 32 + h)) << 12;
        // emit chunk-start state (coalesced on k within v rows)
        for (int idx = tid; idx < 1024; idx += 512) {
            int v = idx >> 4, k4 = (idx & 15) << 2;
            *(float4*)(g_ST + basei + v * 64 + k4) = *(const float4*)(Scur + v * SP + k4);
        }
        if (i == NCHUNK - 1) break;

        const size_t basen = ((size_t)((i + 1) * 32 + h)) << 12;
        // prefetch next G into the other smem buffer, next H into regs
#pragma unroll
        for (int j = 0; j < 2; j++) {
            int seg = tid + j * 512;
            int r = seg >> 4, c4 = (seg & 15) << 2;
            cp_async16(Gnxt + r * SP + c4, g_G + basen + r * 64 + c4);
        }
        cp_commit();
        float hpre[8];
#pragma unroll
        for (int ri = 0; ri < 4; ri++) {
            hpre[ri * 2 + 0] = g_H[basen + (k0 + ri) * 64 + tx];
            hpre[ri * 2 + 1] = g_H[basen + (k0 + ri) * 64 + tx + 32];
        }

        // Snxt[k][v] = sum_j G[k][j] Scur^T[v][j] + H  (4 rows x 2 cols)
        unsigned long long acc[8];
#pragma unroll
        for (int j = 0; j < 8; j++) acc[j] = 0ull;
#pragma unroll 4
        for (int d = 0; d < 64; d += 4) {
            ulonglong2 x0 = *(const ulonglong2*)(Gcur + (k0 + 0) * SP + d);
            ulonglong2 x1 = *(const ulonglong2*)(Gcur + (k0 + 1) * SP + d);
            ulonglong2 x2 = *(const ulonglong2*)(Gcur + (k0 + 2) * SP + d);
            ulonglong2 x3 = *(const ulonglong2*)(Gcur + (k0 + 3) * SP + d);
            ulonglong2 y0 = *(const ulonglong2*)(Scur + (tx +  0) * SP + d);
            ulonglong2 y1 = *(const ulonglong2*)(Scur + (tx + 32) * SP + d);
            ffma2(acc[0], x0.x, y0.x); ffma2(acc[0], x0.y, y0.y);
            ffma2(acc[1], x0.x, y1.x); ffma2(acc[1], x0.y, y1.y);
            ffma2(acc[2], x1.x, y0.x); ffma2(acc[2], x1.y, y0.y);
            ffma2(acc[3], x1.x, y1.x); ffma2(acc[3], x1.y, y1.y);
            ffma2(acc[4], x2.x, y0.x); ffma2(acc[4], x2.y, y0.y);
            ffma2(acc[5], x2.x, y1.x); ffma2(acc[5], x2.y, y1.y);
            ffma2(acc[6], x3.x, y0.x); ffma2(acc[6], x3.y, y0.y);
            ffma2(acc[7], x3.x, y1.x); ffma2(acc[7], x3.y, y1.y);
        }
        // write Snxt transposed [v][k]
#pragma unroll
        for (int c = 0; c < 2; c++) {
            int v = tx + 32 * c;
            float4 o;
            o.x = hsum(acc[0 * 2 + c]) + hcur[0 * 2 + c];
            o.y = hsum(acc[1 * 2 + c]) + hcur[1 * 2 + c];
            o.z = hsum(acc[2 * 2 + c]) + hcur[2 * 2 + c];
            o.w = hsum(acc[3 * 2 + c]) + hcur[3 * 2 + c];
            *(float4*)(Snxt + v * SP + k0) = o;
        }
#pragma unroll
        for (int j = 0; j < 8; j++) hcur[j] = hpre[j];
        cp_wait0();
        __syncthreads();
        float* t1 = Scur; Scur = Snxt; Snxt = t1;
        float* t2 = Gcur; Gcur = Gnxt; Gnxt = t2;
    }
}

// ---------------------------------------------------------------------------
// Kernel 5: O pass (fully parallel). out += Qeff_i @ S_i. 1024 CTAs.
// ---------------------------------------------------------------------------
__global__ __launch_bounds__(256) void opass_kernel(float* __restrict__ out)
{
    __shared__ float sQe[64 * SP];
    __shared__ float sST[64 * SP];

    const int bi = blockIdx.x;
    const int i = bi >> 5;
    const int h = bi & 31;
    const int tid = threadIdx.x;
    const int ty = tid >> 4, tx = tid & 15;
    const int r0 = ty * 4;

    const size_t base = ((size_t)(i * 32 + h)) << 12;
    for (int idx = tid; idx < 1024; idx += 256) {
        int r = idx >> 4, c4 = (idx & 15) << 2;
        float4 q = *(const float4*)(g_Qeff + base + r * 64 + c4);
        sQe[r * SP + c4 + 0] = q.x; sQe[r * SP + c4 + 1] = q.y;
        sQe[r * SP + c4 + 2] = q.z; sQe[r * SP + c4 + 3] = q.w;
        float4 s = *(const float4*)(g_ST + base + r * 64 + c4);
        sST[r * SP + c4 + 0] = s.x; sST[r * SP + c4 + 1] = s.y;
        sST[r * SP + c4 + 2] = s.z; sST[r * SP + c4 + 3] = s.w;
    }
    __syncthreads();

    unsigned long long acc[16];
#pragma unroll
    for (int j = 0; j < 16; j++) acc[j] = 0ull;
    mm64x(sQe, sST, r0, tx, acc);

#pragma unroll
    for (int ri = 0; ri < 4; ri++) {
        int t = r0 + ri;
        float* op = out + (size_t)(i * 64 + t) * 2048 + h * 64;
#pragma unroll
        for (int ci = 0; ci < 4; ci++) {
            int s = tx + 16 * ci;
            op[s] += hsum(acc[ri * 4 + ci]);
        }
    }
}

// ---------------------------------------------------------------------------
extern "C" void kernel_launch(void* const* d_in, const int* in_sizes, int n_in,
                              void* d_out, int out_size)
{
    const float* x    = (const float*)d_in[0];
    const float* cs   = (const float*)d_in[1];
    const float* s0   = (const float*)d_in[2];
    const float* b    = (const float*)d_in[3];
    const float* a    = (const float*)d_in[4];
    const float* w    = (const float*)d_in[5];
    const float* alog = (const float*)d_in[6];
    const float* dtb  = (const float*)d_in[7];

    const int chunk_smem = (6 * 64 * SP + 5 * 64) * sizeof(float);  // ~105.7 KB
    const int state_smem = (4 * 64 * SP) * sizeof(float);           // ~69.6 KB
    static bool attr_done = false;
    if (!attr_done) {
        cudaFuncSetAttribute(chunk_kernel,
                             cudaFuncAttributeMaxDynamicSharedMemorySize, chunk_smem);
        cudaFuncSetAttribute(state_kernel,
                             cudaFuncAttributeMaxDynamicSharedMemorySize, state_smem);
        attr_done = true;
    }

    conv_kernel<<<dim3(4, T_STEPS / 4), 256>>>(x, cs, w);
    gates_kernel<<<(T_STEPS * HV + 255) / 256, 256>>>(b, a, alog, dtb);
    chunk_kernel<<<NCHUNK * HV, 256, chunk_smem>>>((float*)d_out);
    state_kernel<<<HV, 512, state_smem>>>(s0);
    opass_kernel<<<NCHUNK * HV, 256>>>((float*)d_out);
}